// round 12
// baseline (speedup 1.0000x reference)
#include <cuda_runtime.h>
#include <cuda_bf16.h>
#include <cstdint>

// Loss_58042188038797:
//   ri = i / (n*(n+1)/2)
//   p_win = victor==0 ? f[:,0] : f[:,1]
//   loss = -sum( (log(p_win) - (f[:,0]-0.5)^2) * ri )
//
// R11 experiment — last untried axis: CONTIGUOUS PER-CTA CHUNKS instead
// of grid-stride interleaving. Each CTA streams its own ~113KB fo +
// ~57KB pv contiguous region (better DRAM row-buffer / 2MB-page
// locality; one page per ~18 iters vs one per iter). Everything else
// byte-identical to the converged config (plain cached float4/int4,
// BLOCK=256, GRID=148*8 full-occupancy wave, warp+block reduce,
// one atomicAdd per block, memset node zeroes the accumulator).
// Converged baseline (banked best): 34.9us total, kernel 32.1-33.7us,
// DRAM 77-81% = measured LTS cap band.

static constexpr int BLOCK = 256;
static constexpr int GRID  = 148 * 8;

__global__ __launch_bounds__(BLOCK) void loss_kernel(
    const float4* __restrict__ fo,   // final_out as float4: 2 elems per vec
    const int4*  __restrict__ pv,    // point_victor as int4: 4 elems per vec
    float* __restrict__ out,
    int n4,                          // n / 4
    float inv_denom)                 // 2 / (n*(n+1))
{
    float acc = 0.0f;

    // Contiguous chunk per CTA: [chunk_lo, chunk_hi), CTA-local stride BLOCK.
    const int chunk   = (n4 + GRID - 1) / GRID;       // ceil
    const int lo      = blockIdx.x * chunk;
    const int hi_raw  = lo + chunk;
    const int hi      = hi_raw < n4 ? hi_raw : n4;

    for (int i = lo + threadIdx.x; i < hi; i += BLOCK) {
        float4 a = fo[2 * i];        // elems 4i, 4i+1
        float4 b = fo[2 * i + 1];    // elems 4i+2, 4i+3
        int4   v = pv[i];
        float base = (float)(4 * i); // 4i < 2^24 -> exact in f32

        // elem 0: f0=a.x f1=a.y
        {
            float p = (v.x == 0) ? a.x : a.y;
            float d = a.x - 0.5f;
            float t = __logf(p) - d * d;
            acc = fmaf(t, (base + 0.0f) * inv_denom, acc);
        }
        // elem 1: f0=a.z f1=a.w
        {
            float p = (v.y == 0) ? a.z : a.w;
            float d = a.z - 0.5f;
            float t = __logf(p) - d * d;
            acc = fmaf(t, (base + 1.0f) * inv_denom, acc);
        }
        // elem 2: f0=b.x f1=b.y
        {
            float p = (v.z == 0) ? b.x : b.y;
            float d = b.x - 0.5f;
            float t = __logf(p) - d * d;
            acc = fmaf(t, (base + 2.0f) * inv_denom, acc);
        }
        // elem 3: f0=b.z f1=b.w
        {
            float p = (v.w == 0) ? b.z : b.w;
            float d = b.z - 0.5f;
            float t = __logf(p) - d * d;
            acc = fmaf(t, (base + 3.0f) * inv_denom, acc);
        }
    }

    // warp reduce
    #pragma unroll
    for (int o = 16; o > 0; o >>= 1)
        acc += __shfl_down_sync(0xFFFFFFFFu, acc, o);

    __shared__ float smem[BLOCK / 32];
    const int lane = threadIdx.x & 31;
    const int wid  = threadIdx.x >> 5;
    if (lane == 0) smem[wid] = acc;
    __syncthreads();

    if (wid == 0) {
        acc = (lane < BLOCK / 32) ? smem[lane] : 0.0f;
        #pragma unroll
        for (int o = 4; o > 0; o >>= 1)
            acc += __shfl_down_sync(0xFFFFFFFFu, acc, o);
        if (lane == 0)
            atomicAdd(out, -acc);   // loss = -sum
    }
}

extern "C" void kernel_launch(void* const* d_in, const int* in_sizes, int n_in,
                              void* d_out, int out_size) {
    const float4* fo = (const float4*)d_in[0];   // final_out (N,2) f32
    const int4*   pv = (const int4*)d_in[1];     // point_victor (N) i32
    float* out = (float*)d_out;

    const int n = in_sizes[1];                   // N (element count of victor)
    const int n4 = n / 4;                        // N = 2^24, divisible by 4

    // inv_denom = 2 / (n*(n+1)) computed in double on host for accuracy
    const double nd = (double)n;
    const float inv_denom = (float)(2.0 / (nd * (nd + 1.0)));

    // Zero the accumulator via a memset graph node (graph-capturable,
    // allocation-free).
    cudaMemsetAsync(out, 0, sizeof(float));
    loss_kernel<<<GRID, BLOCK>>>(fo, pv, out, n4, inv_denom);
}

// round 13
// speedup vs baseline: 1.0389x; 1.0389x over previous
#include <cuda_runtime.h>
#include <cuda_bf16.h>
#include <cstdint>

// Loss_58042188038797:
//   ri = i / (n*(n+1)/2)
//   p_win = victor==0 ? f[:,0] : f[:,1]
//   loss = -sum( (log(p_win) - (f[:,0]-0.5)^2) * ri )
//
// FINAL — converged at the measured HBM/LTS ceiling (R3-R12, 9 benches).
// This exact config reproduced 34.9us total / kernel 32.1-33.7us /
// DRAM 77.4-80.9% (= documented B300 LTS run-to-run band, ~6300 B/cyc)
// across 5 independent benches. 201 MB read-once traffic is irreducible.
//
// Complete sweep — every deviation measured, every one lost:
//   load policy:    __ldcs streaming        -> 76.1% DRAM (cached wins)
//   MLP/unroll:     2x far-stride unroll    -> 36.2us (1x wins)
//   finish:         fused last-block-done   -> +0.8us tail (2-launch wins)
//   block shape:    512x592                 -> 78.2% DRAM (256x1184 wins)
//   zeroing:        kernel vs memset node   -> tie (memset kept: simpler)
//   addressing:     contiguous per-CTA chunks -> 74.6% DRAM (grid-stride
//                   wins: the sliding window stripes uniformly across all
//                   LTS slices/channels; 1184 spread streams do not)
//
// Config: plain cached float4/int4 grid-stride (MLP_p1=3), BLOCK=256,
// GRID=148*8 (one full-occupancy wave), warp+block reduce, one
// atomicAdd per block, memset graph node zeroes the accumulator.

static constexpr int BLOCK = 256;
static constexpr int GRID  = 148 * 8;

__global__ __launch_bounds__(BLOCK) void loss_kernel(
    const float4* __restrict__ fo,   // final_out as float4: 2 elems per vec
    const int4*  __restrict__ pv,    // point_victor as int4: 4 elems per vec
    float* __restrict__ out,
    int n4,                          // n / 4
    float inv_denom)                 // 2 / (n*(n+1))
{
    float acc = 0.0f;
    const int stride = gridDim.x * blockDim.x;

    for (int i = blockIdx.x * blockDim.x + threadIdx.x; i < n4; i += stride) {
        float4 a = fo[2 * i];        // elems 4i, 4i+1
        float4 b = fo[2 * i + 1];    // elems 4i+2, 4i+3
        int4   v = pv[i];
        float base = (float)(4 * i); // 4i < 2^24 -> exact in f32

        // elem 0: f0=a.x f1=a.y
        {
            float p = (v.x == 0) ? a.x : a.y;
            float d = a.x - 0.5f;
            float t = __logf(p) - d * d;
            acc = fmaf(t, (base + 0.0f) * inv_denom, acc);
        }
        // elem 1: f0=a.z f1=a.w
        {
            float p = (v.y == 0) ? a.z : a.w;
            float d = a.z - 0.5f;
            float t = __logf(p) - d * d;
            acc = fmaf(t, (base + 1.0f) * inv_denom, acc);
        }
        // elem 2: f0=b.x f1=b.y
        {
            float p = (v.z == 0) ? b.x : b.y;
            float d = b.x - 0.5f;
            float t = __logf(p) - d * d;
            acc = fmaf(t, (base + 2.0f) * inv_denom, acc);
        }
        // elem 3: f0=b.z f1=b.w
        {
            float p = (v.w == 0) ? b.z : b.w;
            float d = b.z - 0.5f;
            float t = __logf(p) - d * d;
            acc = fmaf(t, (base + 3.0f) * inv_denom, acc);
        }
    }

    // warp reduce
    #pragma unroll
    for (int o = 16; o > 0; o >>= 1)
        acc += __shfl_down_sync(0xFFFFFFFFu, acc, o);

    __shared__ float smem[BLOCK / 32];
    const int lane = threadIdx.x & 31;
    const int wid  = threadIdx.x >> 5;
    if (lane == 0) smem[wid] = acc;
    __syncthreads();

    if (wid == 0) {
        acc = (lane < BLOCK / 32) ? smem[lane] : 0.0f;
        #pragma unroll
        for (int o = 4; o > 0; o >>= 1)
            acc += __shfl_down_sync(0xFFFFFFFFu, acc, o);
        if (lane == 0)
            atomicAdd(out, -acc);   // loss = -sum
    }
}

extern "C" void kernel_launch(void* const* d_in, const int* in_sizes, int n_in,
                              void* d_out, int out_size) {
    const float4* fo = (const float4*)d_in[0];   // final_out (N,2) f32
    const int4*   pv = (const int4*)d_in[1];     // point_victor (N) i32
    float* out = (float*)d_out;

    const int n = in_sizes[1];                   // N (element count of victor)
    const int n4 = n / 4;                        // N = 2^24, divisible by 4

    // inv_denom = 2 / (n*(n+1)) computed in double on host for accuracy
    const double nd = (double)n;
    const float inv_denom = (float)(2.0 / (nd * (nd + 1.0)));

    // Zero the accumulator via a memset graph node (graph-capturable,
    // allocation-free; measured equal-best vs a 1-thread zero kernel).
    cudaMemsetAsync(out, 0, sizeof(float));
    loss_kernel<<<GRID, BLOCK>>>(fo, pv, out, n4, inv_denom);
}

// round 14
// speedup vs baseline: 1.0640x; 1.0241x over previous
#include <cuda_runtime.h>
#include <cuda_bf16.h>
#include <cstdint>

// Loss_58042188038797:
//   ri = i / (n*(n+1)/2)
//   p_win = victor==0 ? f[:,0] : f[:,1]
//   loss = -sum( (log(p_win) - (f[:,0]-0.5)^2) * ri )
//
// FINAL — converged at the measured HBM/LTS ceiling (R3-R13, 10 benches).
// This exact config: total 34.9 +/- 0.6us across 6 benches, kernel
// 32.1-33.7us, DRAM 77.4-80.9% (= B300 LTS run-to-run band, ~6300 B/cyc).
// Roofline: 201 MB irreducible read-once traffic / ~6.2 TB/s measured cap
// = ~32.5us kernel floor + ~2.3us fixed graph/harness overhead.
//
// Closed axes (all measured, all lost vs this config):
//   __ldcs streaming (76.1% DRAM) | 2x far-stride unroll (36.2us) |
//   fused last-block-done (+0.8us) | BLOCK=512 (78.2%) |
//   contiguous per-CTA chunks (74.6%) | memset-vs-kernel zeroing (tie).
// Structurally closed: grid = 148*8x256 = 2048 thr/SM = HW max, one
// wave; victor i32 read irreducible (format fixed by harness); LTS cap
// is path-independent (LDG == TMA) so no async path can beat it.

static constexpr int BLOCK = 256;
static constexpr int GRID  = 148 * 8;

__global__ __launch_bounds__(BLOCK) void loss_kernel(
    const float4* __restrict__ fo,   // final_out as float4: 2 elems per vec
    const int4*  __restrict__ pv,    // point_victor as int4: 4 elems per vec
    float* __restrict__ out,
    int n4,                          // n / 4
    float inv_denom)                 // 2 / (n*(n+1))
{
    float acc = 0.0f;
    const int stride = gridDim.x * blockDim.x;

    for (int i = blockIdx.x * blockDim.x + threadIdx.x; i < n4; i += stride) {
        float4 a = fo[2 * i];        // elems 4i, 4i+1
        float4 b = fo[2 * i + 1];    // elems 4i+2, 4i+3
        int4   v = pv[i];
        float base = (float)(4 * i); // 4i < 2^24 -> exact in f32

        // elem 0: f0=a.x f1=a.y
        {
            float p = (v.x == 0) ? a.x : a.y;
            float d = a.x - 0.5f;
            float t = __logf(p) - d * d;
            acc = fmaf(t, (base + 0.0f) * inv_denom, acc);
        }
        // elem 1: f0=a.z f1=a.w
        {
            float p = (v.y == 0) ? a.z : a.w;
            float d = a.z - 0.5f;
            float t = __logf(p) - d * d;
            acc = fmaf(t, (base + 1.0f) * inv_denom, acc);
        }
        // elem 2: f0=b.x f1=b.y
        {
            float p = (v.z == 0) ? b.x : b.y;
            float d = b.x - 0.5f;
            float t = __logf(p) - d * d;
            acc = fmaf(t, (base + 2.0f) * inv_denom, acc);
        }
        // elem 3: f0=b.z f1=b.w
        {
            float p = (v.w == 0) ? b.z : b.w;
            float d = b.z - 0.5f;
            float t = __logf(p) - d * d;
            acc = fmaf(t, (base + 3.0f) * inv_denom, acc);
        }
    }

    // warp reduce
    #pragma unroll
    for (int o = 16; o > 0; o >>= 1)
        acc += __shfl_down_sync(0xFFFFFFFFu, acc, o);

    __shared__ float smem[BLOCK / 32];
    const int lane = threadIdx.x & 31;
    const int wid  = threadIdx.x >> 5;
    if (lane == 0) smem[wid] = acc;
    __syncthreads();

    if (wid == 0) {
        acc = (lane < BLOCK / 32) ? smem[lane] : 0.0f;
        #pragma unroll
        for (int o = 4; o > 0; o >>= 1)
            acc += __shfl_down_sync(0xFFFFFFFFu, acc, o);
        if (lane == 0)
            atomicAdd(out, -acc);   // loss = -sum
    }
}

extern "C" void kernel_launch(void* const* d_in, const int* in_sizes, int n_in,
                              void* d_out, int out_size) {
    const float4* fo = (const float4*)d_in[0];   // final_out (N,2) f32
    const int4*   pv = (const int4*)d_in[1];     // point_victor (N) i32
    float* out = (float*)d_out;

    const int n = in_sizes[1];                   // N (element count of victor)
    const int n4 = n / 4;                        // N = 2^24, divisible by 4

    // inv_denom = 2 / (n*(n+1)) computed in double on host for accuracy
    const double nd = (double)n;
    const float inv_denom = (float)(2.0 / (nd * (nd + 1.0)));

    // Zero the accumulator via a memset graph node (graph-capturable,
    // allocation-free; measured equal-best vs a 1-thread zero kernel).
    cudaMemsetAsync(out, 0, sizeof(float));
    loss_kernel<<<GRID, BLOCK>>>(fo, pv, out, n4, inv_denom);
}